// round 15
// baseline (speedup 1.0000x reference)
#include <cuda_runtime.h>
#include <cuda_bf16.h>
#include <cstdint>

// Decoder (Conv-TasNet): out = overlap_add( (mixture_w * est_mask)^T @ W^T, step=L/2 )
// mixture_w/est_mask [B, N, K] f32, W [L, N] f32, out [B, T] f32
// B=4, N=512, K=16000, L=16, step=8, T = 8*(K-1)+16 = 128008
//
// R15 = R7 datapath + register double-buffer whose prefetch is pinned by a
// __syncthreads() between load-issue and compute (ptxas cannot sink memory
// ops across BAR.SYNC -- this defeats the R8 silent-sink failure). Each warp
// keeps 2KB in flight during the whole compute phase, and the 4 warps of a
// block issue their batches in lockstep (1KB-contiguous DRAM row visits).

#define DEC_B 4
#define DEC_N 512
#define DEC_K 16000
#define DEC_L 16
#define DEC_STEP 8
#define DEC_T (DEC_STEP * (DEC_K - 1) + DEC_L)   // 128008

#define TPB 128
#define NSPLIT 4
#define NCHUNK (DEC_N / NSPLIT)      // 128
#define KPT 2                         // frames per thread (float2 along k)
#define NB 4                          // n's per batch (8 LDG.64 in flight)
#define NACC 12                       // f32x2 accumulators (24 out positions)

typedef unsigned long long u64t;

#define FMA_F32X2(d, a, b, c) \
    asm("fma.rn.f32x2 %0, %1, %2, %3;" : "=l"(d) : "l"(a), "l"(b), "l"(c))

__global__ __launch_bounds__(TPB, 6)
void decoder_kernel(const float* __restrict__ mw,
                    const float* __restrict__ em,
                    const float* __restrict__ W,
                    float* __restrict__ out)
{
    // This block's N-chunk of W, transposed: Ws[n_local][l]. 8 KB.
    __shared__ __align__(16) float Ws[NCHUNK * DEC_L];
    const int nb = blockIdx.z * NCHUNK;
    for (int i = threadIdx.x; i < NCHUNK * DEC_L; i += TPB) {
        int n = i >> 4;
        int l = i & 15;
        Ws[i] = W[l * DEC_N + nb + n];
    }
    __syncthreads();

    const int b = blockIdx.y;
    int k0 = (blockIdx.x * TPB + threadIdx.x) * KPT;
    const bool valid = (k0 < DEC_K);
    if (!valid) k0 = 0;   // clamped duplicate work; output suppressed.
                          // NO early return: all threads must reach barriers.

    const size_t base = (size_t)b * DEC_N * DEC_K + (size_t)nb * DEC_K + k0;
    const float2* __restrict__ mwp = reinterpret_cast<const float2*>(mw + base);
    const float2* __restrict__ emp = reinterpret_cast<const float2*>(em + base);
    const size_t kstr = DEC_K / 2;   // float2 stride between n rows

    // 24 fp32 accumulators as 12 x f32x2. Frame k0 -> accp[0..7],
    // frame k0+1 -> accp[4..11] (overlap of 8 positions = 4 pairs).
    u64t accp[NACC];
#pragma unroll
    for (int i = 0; i < NACC; ++i) accp[i] = 0ull;

    // One n-step: 2 FMUL + 2 packs + 4 LDS.128 + 16 FFMA2.
    auto step = [&](int n, float2 m, float2 e) {
        float p0 = m.x * e.x;
        float p1 = m.y * e.y;
        u64t pp0, pp1;
        asm("mov.b64 %0, {%1, %1};" : "=l"(pp0) : "f"(p0));
        asm("mov.b64 %0, {%1, %1};" : "=l"(pp1) : "f"(p1));

        const ulonglong2* w = reinterpret_cast<const ulonglong2*>(&Ws[n * DEC_L]);
        ulonglong2 w0 = w[0];
        ulonglong2 w1 = w[1];
        ulonglong2 w2 = w[2];
        ulonglong2 w3 = w[3];

        FMA_F32X2(accp[0],  w0.x, pp0, accp[0]);
        FMA_F32X2(accp[1],  w0.y, pp0, accp[1]);
        FMA_F32X2(accp[2],  w1.x, pp0, accp[2]);
        FMA_F32X2(accp[3],  w1.y, pp0, accp[3]);
        FMA_F32X2(accp[4],  w2.x, pp0, accp[4]);
        FMA_F32X2(accp[5],  w2.y, pp0, accp[5]);
        FMA_F32X2(accp[6],  w3.x, pp0, accp[6]);
        FMA_F32X2(accp[7],  w3.y, pp0, accp[7]);
        FMA_F32X2(accp[4],  w0.x, pp1, accp[4]);
        FMA_F32X2(accp[5],  w0.y, pp1, accp[5]);
        FMA_F32X2(accp[6],  w1.x, pp1, accp[6]);
        FMA_F32X2(accp[7],  w1.y, pp1, accp[7]);
        FMA_F32X2(accp[8],  w2.x, pp1, accp[8]);
        FMA_F32X2(accp[9],  w2.y, pp1, accp[9]);
        FMA_F32X2(accp[10], w3.x, pp1, accp[10]);
        FMA_F32X2(accp[11], w3.y, pp1, accp[11]);
    };

    // Prologue: batch 0 in flight.
    float2 mA[NB], eA[NB], mB[NB], eB[NB];
#pragma unroll
    for (int j = 0; j < NB; ++j) {
        mA[j] = __ldcs(&mwp[(size_t)j * kstr]);
        eA[j] = __ldcs(&emp[(size_t)j * kstr]);
    }

#pragma unroll 1
    for (int n0 = 0; n0 < NCHUNK; n0 += 2 * NB) {
        // issue batch B, then barrier: prefetch cannot sink past BAR.SYNC,
        // so B's 8 LDG.64 stay in flight across the whole compute-A phase.
#pragma unroll
        for (int j = 0; j < NB; ++j) {
            mB[j] = __ldcs(&mwp[(size_t)(n0 + NB + j) * kstr]);
            eB[j] = __ldcs(&emp[(size_t)(n0 + NB + j) * kstr]);
        }
        __syncthreads();
#pragma unroll
        for (int j = 0; j < NB; ++j) step(n0 + j, mA[j], eA[j]);

        if (n0 + 2 * NB < NCHUNK) {
#pragma unroll
            for (int j = 0; j < NB; ++j) {
                mA[j] = __ldcs(&mwp[(size_t)(n0 + 2 * NB + j) * kstr]);
                eA[j] = __ldcs(&emp[(size_t)(n0 + 2 * NB + j) * kstr]);
            }
        }
        __syncthreads();
#pragma unroll
        for (int j = 0; j < NB; ++j) step(n0 + NB + j, mB[j], eB[j]);
    }

    // Scatter-add 24 unique positions (frames k0, k0+1). <= 2*NSPLIT = 8 fp32
    // contributions per output element (atomic, order-insensitive).
    if (valid) {
        float* __restrict__ op = out + (size_t)b * DEC_T + (size_t)k0 * DEC_STEP;
#pragma unroll
        for (int i = 0; i < NACC; ++i) {
            float lo, hi;
            asm("mov.b64 {%0, %1}, %2;" : "=f"(lo), "=f"(hi) : "l"(accp[i]));
            atomicAdd(&op[2 * i],     lo);
            atomicAdd(&op[2 * i + 1], hi);
        }
    }
}

extern "C" void kernel_launch(void* const* d_in, const int* in_sizes, int n_in,
                              void* d_out, int out_size)
{
    const float* mixture_w = (const float*)d_in[0];  // [B, N, K]
    const float* est_mask  = (const float*)d_in[1];  // [B, N, K]
    const float* W         = (const float*)d_in[2];  // [L, N]
    float* out = (float*)d_out;                       // [B, T]

    cudaMemsetAsync(out, 0, (size_t)out_size * sizeof(float), 0);

    dim3 grid((DEC_K + TPB * KPT - 1) / (TPB * KPT), DEC_B, NSPLIT);  // (63, 4, 4)
    decoder_kernel<<<grid, TPB>>>(mixture_w, est_mask, W, out);
}

// round 16
// speedup vs baseline: 1.3292x; 1.3292x over previous
#include <cuda_runtime.h>
#include <cuda_bf16.h>
#include <cstdint>

// Decoder (Conv-TasNet): out = overlap_add( (mixture_w * est_mask)^T @ W^T, step=L/2 )
// mixture_w/est_mask [B, N, K] f32, W [L, N] f32, out [B, T] f32
// B=4, N=512, K=16000, L=16, step=8, T = 8*(K-1)+16 = 128008
//
// R16: per-THREAD cp.async pipeline (no barriers, no syncwarp in the loop).
// Each lane async-copies exactly the 16B it later reads, 8-stage ring ->
// ~7KB/warp in flight CONTINUOUSLY, decoupled from registers and warp count
// (the constraint that pinned R2..R15 at ~28 GB/s/SM). KPT=4 FFMA2 datapath.
// 16000 = 125 warps x 128 k exactly: no tail threads.

#define DEC_B 4
#define DEC_N 512
#define DEC_K 16000
#define DEC_L 16
#define DEC_STEP 8
#define DEC_T (DEC_STEP * (DEC_K - 1) + DEC_L)   // 128008

#define TPB 160                       // 5 warps; block covers 640 k
#define NSPLIT 4
#define NCHUNK (DEC_N / NSPLIT)       // 128 n-rows per block
#define KPT 4                         // frames per thread
#define KPW 128                       // k per warp (32 lanes x 4)
#define DEPTH 8                       // cp.async ring stages
#define NACC 20                       // f32x2 accumulators (40 out positions)

// smem: Ws = 2048 floats (8KB); ring = 5 warps x 8 stages x 1KB (m 512B + e 512B)
#define SMEM_WS_FLOATS 2048
#define SMEM_TOTAL_FLOATS (SMEM_WS_FLOATS + 5 * DEPTH * 256)   // 12288 = 48KB

typedef unsigned long long u64t;

#define FMA_F32X2(d, a, b, c) \
    asm("fma.rn.f32x2 %0, %1, %2, %3;" : "=l"(d) : "l"(a), "l"(b), "l"(c))

#define CP16(dst_u32, src_ptr) \
    asm volatile("cp.async.cg.shared.global [%0], [%1], 16;" \
                 :: "r"(dst_u32), "l"(src_ptr) : "memory")
#define CP_COMMIT() asm volatile("cp.async.commit_group;" ::: "memory")
#define CP_WAIT(n)  asm volatile("cp.async.wait_group %0;" :: "n"(n) : "memory")

__global__ __launch_bounds__(TPB)
void decoder_kernel(const float* __restrict__ mw,
                    const float* __restrict__ em,
                    const float* __restrict__ W,
                    float* __restrict__ out)
{
    __shared__ __align__(16) float smem[SMEM_TOTAL_FLOATS];
    float* Ws = smem;   // [128][16] transposed W chunk

    const int nb = blockIdx.z * NCHUNK;
    for (int i = threadIdx.x; i < NCHUNK * DEC_L; i += TPB) {
        int n = i >> 4;
        int l = i & 15;
        Ws[i] = W[l * DEC_N + nb + n];
    }
    __syncthreads();    // only sync in the kernel (W visibility)

    const int w    = threadIdx.x >> 5;
    const int lane = threadIdx.x & 31;
    const int b    = blockIdx.y;
    const int k0   = blockIdx.x * (TPB * KPT) + w * KPW + lane * KPT;  // < 16000 always

    // Per-thread global cursors: this lane's 16B slot in row n.
    const size_t base = (size_t)b * DEC_N * DEC_K + (size_t)nb * DEC_K + k0;
    const float* im = mw + base;
    const float* ie = em + base;

    // Per-thread smem slot addresses (byte offsets from smem base).
    uint32_t sb;
    {
        void* p = smem;
        asm("{ .reg .u64 t; cvta.to.shared.u64 t, %1; cvt.u32.u64 %0, t; }"
            : "=r"(sb) : "l"(p));
    }
    // ring base for this thread: after Ws (8192B), warp region 8KB, lane slot 16B
    const uint32_t rbase = sb + 8192u + (uint32_t)w * (DEPTH * 1024u) + (uint32_t)lane * 16u;

    // Prologue: stages 0..DEPTH-2 in flight (7KB/warp).
#pragma unroll
    for (int s = 0; s < DEPTH - 1; ++s) {
        uint32_t d = rbase + (uint32_t)s * 1024u;
        CP16(d, im);
        CP16(d + 512u, ie);
        im += DEC_K;
        ie += DEC_K;
        CP_COMMIT();
    }

    // 40 fp32 out positions as 20 f32x2 pairs. Frame f (0..3) covers
    // positions 8f..8f+15 = pairs 4f..4f+7.
    u64t accp[NACC];
#pragma unroll
    for (int i = 0; i < NACC; ++i) accp[i] = 0ull;

#pragma unroll 1
    for (int n = 0; n < NCHUNK; ++n) {
        // issue stage n+DEPTH-1 (own 16B only), commit ALWAYS (group accounting)
        if (n + DEPTH - 1 < NCHUNK) {
            uint32_t d = rbase + (uint32_t)((n + DEPTH - 1) & (DEPTH - 1)) * 1024u;
            CP16(d, im);
            CP16(d + 512u, ie);
            im += DEC_K;
            ie += DEC_K;
        }
        CP_COMMIT();
        CP_WAIT(DEPTH - 1);   // oldest group (stage n) complete for THIS thread

        uint32_t r = rbase + (uint32_t)(n & (DEPTH - 1)) * 1024u;
        float4 m, e;
        asm volatile("ld.shared.v4.f32 {%0,%1,%2,%3}, [%4];"
                     : "=f"(m.x), "=f"(m.y), "=f"(m.z), "=f"(m.w) : "r"(r));
        asm volatile("ld.shared.v4.f32 {%0,%1,%2,%3}, [%4];"
                     : "=f"(e.x), "=f"(e.y), "=f"(e.z), "=f"(e.w) : "r"(r + 512u));

        // compute: 4 FMUL + 4 packs + 4 LDS.128 (W, broadcast) + 32 FFMA2
        float p0 = m.x * e.x;
        float p1 = m.y * e.y;
        float p2 = m.z * e.z;
        float p3 = m.w * e.w;
        u64t pp[KPT];
        asm("mov.b64 %0, {%1, %1};" : "=l"(pp[0]) : "f"(p0));
        asm("mov.b64 %0, {%1, %1};" : "=l"(pp[1]) : "f"(p1));
        asm("mov.b64 %0, {%1, %1};" : "=l"(pp[2]) : "f"(p2));
        asm("mov.b64 %0, {%1, %1};" : "=l"(pp[3]) : "f"(p3));

        const ulonglong2* wq = reinterpret_cast<const ulonglong2*>(&Ws[n * DEC_L]);
#pragma unroll
        for (int q = 0; q < 4; ++q) {
            ulonglong2 w2 = wq[q];      // pairs j = 2q, 2q+1
#pragma unroll
            for (int f = 0; f < KPT; ++f) {
                FMA_F32X2(accp[4 * f + 2 * q],     w2.x, pp[f], accp[4 * f + 2 * q]);
                FMA_F32X2(accp[4 * f + 2 * q + 1], w2.y, pp[f], accp[4 * f + 2 * q + 1]);
            }
        }
    }

    // Scatter-add 40 unique positions (frames k0..k0+3). Interior overlaps
    // merged in registers; <= 2*NSPLIT = 8 atomic fp32 contributions per
    // output element (order-insensitive).
    float* __restrict__ op = out + (size_t)b * DEC_T + (size_t)k0 * DEC_STEP;
#pragma unroll
    for (int i = 0; i < NACC; ++i) {
        float lo, hi;
        asm("mov.b64 {%0, %1}, %2;" : "=f"(lo), "=f"(hi) : "l"(accp[i]));
        atomicAdd(&op[2 * i],     lo);
        atomicAdd(&op[2 * i + 1], hi);
    }
}

extern "C" void kernel_launch(void* const* d_in, const int* in_sizes, int n_in,
                              void* d_out, int out_size)
{
    const float* mixture_w = (const float*)d_in[0];  // [B, N, K]
    const float* est_mask  = (const float*)d_in[1];  // [B, N, K]
    const float* W         = (const float*)d_in[2];  // [L, N]
    float* out = (float*)d_out;                       // [B, T]

    cudaMemsetAsync(out, 0, (size_t)out_size * sizeof(float), 0);

    dim3 grid(DEC_K / (TPB * KPT), DEC_B, NSPLIT);   // (25, 4, 4) = 400 blocks
    decoder_kernel<<<grid, TPB>>>(mixture_w, est_mask, W, out);
}